// round 1
// baseline (speedup 1.0000x reference)
#include <cuda_runtime.h>
#include <math.h>

#define S_DIM 512
#define I_DIM 384
#define C_DIM 256
#define H_DIM 8
#define D_DIM 32
#define TD_DIM 256
#define R_DIM (S_DIM * I_DIM)   /* 196608 rows (s,i) */
#define LN_EPS 1e-5f

/* ---------------- scratch (device globals: allocation-free) ---------------- */
__device__ float g_xln[R_DIM * C_DIM];            /* 201 MB : LN(x) rows       */
__device__ float g_scores[H_DIM * I_DIM * S_DIM]; /* [h][i][s]                 */
__device__ float g_attn[I_DIM * H_DIM * S_DIM];   /* [i][h][s]                 */
__device__ float g_mean[I_DIM * C_DIM];           /* column mean of raw x      */
__device__ float g_wkq[I_DIM * H_DIM * C_DIM];    /* Wk @ Q[i,h,:]             */
__device__ float g_weighted[I_DIM * TD_DIM];      /* attn-weighted V           */

/* ============ A: mean over s of raw input -> g_mean[i*C + c] ============ */
__global__ void mean_kernel(const float* __restrict__ x) {
    int idx = blockIdx.x * 256 + threadIdx.x;   /* over I*C = 98304 */
    const float* p = x + idx;
    float acc = 0.f;
#pragma unroll 8
    for (int s = 0; s < S_DIM; ++s) acc += p[s * (I_DIM * C_DIM)];
    g_mean[idx] = acc * (1.0f / S_DIM);
}

/* ============ B: LN(mean) -> Q -> Wkq[i,h,c] (one block per i) ============ */
__global__ void qprep_kernel(const float* __restrict__ ln_w, const float* __restrict__ ln_b,
                             const float* __restrict__ Wq, const float* __restrict__ Wk) {
    __shared__ float sX[C_DIM];
    __shared__ float sQ[TD_DIM];
    __shared__ float sWk[32 * C_DIM];
    __shared__ float red1[8];
    __shared__ float red2[8];
    int t = threadIdx.x;
    int i = blockIdx.x;
    int lane = t & 31, warp = t >> 5;

    float v = g_mean[i * C_DIM + t];
    float sum = v;
#pragma unroll
    for (int o = 16; o; o >>= 1) sum += __shfl_xor_sync(~0u, sum, o);
    if (lane == 0) red1[warp] = sum;
    __syncthreads();
    float tot = red1[0] + red1[1] + red1[2] + red1[3] + red1[4] + red1[5] + red1[6] + red1[7];
    float mu = tot * (1.0f / C_DIM);
    float d = v - mu;
    float sq = d * d;
#pragma unroll
    for (int o = 16; o; o >>= 1) sq += __shfl_xor_sync(~0u, sq, o);
    if (lane == 0) red2[warp] = sq;
    __syncthreads();
    float tot2 = red2[0] + red2[1] + red2[2] + red2[3] + red2[4] + red2[5] + red2[6] + red2[7];
    float var = tot2 * (1.0f / C_DIM);
    float xn = d * rsqrtf(var + LN_EPS) * ln_w[t] + ln_b[t];
    sX[t] = xn;
    __syncthreads();

    /* Q[td] = sX . Wq[:, td] */
    float q = 0.f;
#pragma unroll 4
    for (int c = 0; c < C_DIM; ++c) q += sX[c] * Wq[c * TD_DIM + t];
    sQ[t] = q;
    __syncthreads();

    /* Wkq[i,h,c] = sum_d Q[h*32+d] * Wk[c, h*32+d]   (stage Wk rows in smem) */
    for (int ch = 0; ch < 8; ++ch) {
#pragma unroll
        for (int p = 0; p < 32; ++p) {
            int idx = p * 256 + t;
            sWk[idx] = Wk[(ch * 32) * C_DIM + idx];
        }
        __syncthreads();
        int cl = t >> 3, h = t & 7;
        float a = 0.f;
#pragma unroll
        for (int dd = 0; dd < 32; ++dd)
            a += sQ[h * 32 + dd] * sWk[cl * C_DIM + h * 32 + dd];
        g_wkq[(i * H_DIM + h) * C_DIM + ch * 32 + cl] = a;
        __syncthreads();
    }
}

/* ===== C: per-row LN -> write g_xln; scores[h] = xln . Wkq[i,h,:] (warp/row) ===== */
__global__ void ln_score_kernel(const float* __restrict__ x, const float* __restrict__ mask,
                                const float* __restrict__ ln_w, const float* __restrict__ ln_b) {
    int lane = threadIdx.x & 31;
    int r = blockIdx.x * 8 + (threadIdx.x >> 5);
    int s = r / I_DIM;
    int i = r - s * I_DIM;
    const float* row = x + (size_t)r * C_DIM;

    float xv[8];
#pragma unroll
    for (int j = 0; j < 8; ++j) xv[j] = row[j * 32 + lane];
    float sum = 0.f;
#pragma unroll
    for (int j = 0; j < 8; ++j) sum += xv[j];
#pragma unroll
    for (int o = 16; o; o >>= 1) sum += __shfl_xor_sync(~0u, sum, o);
    float mu = sum * (1.0f / C_DIM);
    float dv[8], sq = 0.f;
#pragma unroll
    for (int j = 0; j < 8; ++j) { dv[j] = xv[j] - mu; sq += dv[j] * dv[j]; }
#pragma unroll
    for (int o = 16; o; o >>= 1) sq += __shfl_xor_sync(~0u, sq, o);
    float rstd = rsqrtf(sq * (1.0f / C_DIM) + LN_EPS);

    float xn[8];
    float* xo = g_xln + (size_t)r * C_DIM;
#pragma unroll
    for (int j = 0; j < 8; ++j) {
        xn[j] = dv[j] * rstd * ln_w[j * 32 + lane] + ln_b[j * 32 + lane];
        xo[j * 32 + lane] = xn[j];
    }

    const float inv_sqrt_d = 0.17677669529663687f; /* 1/sqrt(32) */
    float my_score = 0.f;
#pragma unroll
    for (int h = 0; h < 8; ++h) {
        const float* wk = g_wkq + ((i * H_DIM + h) << 8);
        float p = 0.f;
#pragma unroll
        for (int j = 0; j < 8; ++j) p += xn[j] * wk[j * 32 + lane];
#pragma unroll
        for (int o = 16; o; o >>= 1) p += __shfl_xor_sync(~0u, p, o);
        if (lane == h) my_score = p;
    }
    if (lane < 8) {
        float sc = my_score * inv_sqrt_d + (1.0f - mask[r]) * (-1e9f);
        g_scores[(lane * I_DIM + i) * S_DIM + s] = sc;
    }
}

/* ============ D: softmax over s (block per (h,i)) ============ */
__global__ void softmax_kernel() {
    __shared__ float red[8];
    int bx = blockIdx.x;
    int h = bx / I_DIM;
    int i = bx - h * I_DIM;
    int t = threadIdx.x;
    int lane = t & 31, warp = t >> 5;

    const float* sp = g_scores + (h * I_DIM + i) * S_DIM;
    float v0 = sp[t], v1 = sp[t + 256];
    float m = fmaxf(v0, v1);
#pragma unroll
    for (int o = 16; o; o >>= 1) m = fmaxf(m, __shfl_xor_sync(~0u, m, o));
    if (lane == 0) red[warp] = m;
    __syncthreads();
    m = red[0];
#pragma unroll
    for (int k = 1; k < 8; ++k) m = fmaxf(m, red[k]);
    __syncthreads();
    float e0 = __expf(v0 - m), e1 = __expf(v1 - m);
    float sum = e0 + e1;
#pragma unroll
    for (int o = 16; o; o >>= 1) sum += __shfl_xor_sync(~0u, sum, o);
    if (lane == 0) red[warp] = sum;
    __syncthreads();
    float tot = red[0] + red[1] + red[2] + red[3] + red[4] + red[5] + red[6] + red[7];
    float inv = 1.0f / tot;
    float* op = g_attn + (i * H_DIM + h) * S_DIM;
    op[t] = e0 * inv;
    op[t + 256] = e1 * inv;
}

/* ===== E: Y[i,h,c] = sum_s attn*xln ; weighted[i,h,d] = Y . Wv (block per i) ===== */
__global__ void weighted_kernel(const float* __restrict__ Wv) {
    __shared__ float sA[H_DIM * S_DIM];  /* 16 KB */
    __shared__ float sY[H_DIM * C_DIM];  /*  8 KB */
    int t = threadIdx.x;
    int i = blockIdx.x;
    const float* ap = g_attn + i * H_DIM * S_DIM;
#pragma unroll
    for (int p = 0; p < 16; ++p) sA[p * 256 + t] = ap[p * 256 + t];
    __syncthreads();

    float Y[8];
#pragma unroll
    for (int h = 0; h < 8; ++h) Y[h] = 0.f;
    const float* xp = g_xln + i * C_DIM + t;
#pragma unroll 4
    for (int s2 = 0; s2 < S_DIM; ++s2) {
        float xv = xp[(size_t)s2 * I_DIM * C_DIM];
#pragma unroll
        for (int h = 0; h < 8; ++h) Y[h] += sA[h * S_DIM + s2] * xv;
    }
#pragma unroll
    for (int h = 0; h < 8; ++h) sY[h * C_DIM + t] = Y[h];
    __syncthreads();

    int h = t >> 5, d = t & 31;
    float w = 0.f;
    const float* yp = sY + h * C_DIM;
    const float* wp = Wv + h * 32 + d;
#pragma unroll 4
    for (int c = 0; c < C_DIM; ++c) w += yp[c] * wp[c * TD_DIM];
    g_weighted[i * TD_DIM + t] = w;
}

/* ===== F: out = (sigmoid(xln@Wg+bg) * weighted[i]) @ Wo + bo, * mask =====
   64-row x 256-col block tile, 8x8 per thread, two chained GEMMs via smem. */
__global__ void __launch_bounds__(256, 1)
out_kernel(const float* __restrict__ Wg, const float* __restrict__ bg,
           const float* __restrict__ Wo, const float* __restrict__ bo,
           const float* __restrict__ mask, float* __restrict__ out) {
    extern __shared__ float sm[];
    float* sX = sm;                 /* 64 x 68  */
    float* sW = sX + 64 * 68;       /* 64 x 256 */
    float* sG = sW + 64 * 256;      /* 64 x 256 */
    float* sBg = sG + 64 * 256;     /* 256      */
    float* sBo = sBg + 256;         /* 256      */
    float* sMask = sBo + 256;       /* 64       */

    int t = threadIdx.x;
    int row0 = blockIdx.x * 64;
    int cg = t & 31, rg = t >> 5;
    int cA = cg * 4, cB = 128 + cg * 4;

    sBg[t] = bg[t];
    sBo[t] = bo[t];
    if (t < 64) sMask[t] = mask[row0 + t];

    float acc[64];
#pragma unroll
    for (int q = 0; q < 64; ++q) acc[q] = 0.f;

    const float* xbase = g_xln + (size_t)row0 * C_DIM;

    /* ---- GEMM1: xln @ Wg ---- */
    for (int kc = 0; kc < 256; kc += 64) {
        __syncthreads();
#pragma unroll
        for (int p = 0; p < 4; ++p) {
            int idx = p * 256 + t;
            int rr = idx >> 4, f4 = idx & 15;
            float4 v = *(const float4*)(xbase + rr * 256 + kc + f4 * 4);
            *(float4*)(sX + rr * 68 + f4 * 4) = v;
        }
#pragma unroll
        for (int p = 0; p < 16; ++p) {
            int idx = p * 256 + t;
            int kk = idx >> 6, c4 = idx & 63;
            float4 v = *(const float4*)(Wg + (kc + kk) * 256 + c4 * 4);
            *(float4*)(sW + kk * 256 + c4 * 4) = v;
        }
        __syncthreads();
#pragma unroll 4
        for (int k = 0; k < 64; ++k) {
            float a[8];
#pragma unroll
            for (int j = 0; j < 8; ++j) a[j] = sX[(rg * 8 + j) * 68 + k];
            float4 b0 = *(float4*)(sW + k * 256 + cA);
            float4 b1 = *(float4*)(sW + k * 256 + cB);
#pragma unroll
            for (int j = 0; j < 8; ++j) {
                acc[j * 8 + 0] += a[j] * b0.x; acc[j * 8 + 1] += a[j] * b0.y;
                acc[j * 8 + 2] += a[j] * b0.z; acc[j * 8 + 3] += a[j] * b0.w;
                acc[j * 8 + 4] += a[j] * b1.x; acc[j * 8 + 5] += a[j] * b1.y;
                acc[j * 8 + 6] += a[j] * b1.z; acc[j * 8 + 7] += a[j] * b1.w;
            }
        }
    }

    /* ---- epilogue 1: sigmoid + gate, write sG ---- */
#pragma unroll
    for (int j = 0; j < 8; ++j) {
        int rl = rg * 8 + j;
        int row = row0 + rl;
        int i = row % I_DIM;
        const float* wt = g_weighted + i * TD_DIM;
#pragma unroll
        for (int cc = 0; cc < 4; ++cc) {
            int col = cA + cc;
            float v = acc[j * 8 + cc] + sBg[col];
            float g = 1.0f / (1.0f + __expf(-v));
            sG[rl * 256 + col] = g * wt[col];
        }
#pragma unroll
        for (int cc = 0; cc < 4; ++cc) {
            int col = cB + cc;
            float v = acc[j * 8 + 4 + cc] + sBg[col];
            float g = 1.0f / (1.0f + __expf(-v));
            sG[rl * 256 + col] = g * wt[col];
        }
    }
#pragma unroll
    for (int q = 0; q < 64; ++q) acc[q] = 0.f;

    /* ---- GEMM2: gated @ Wo ---- */
    for (int kc = 0; kc < 256; kc += 64) {
        __syncthreads();   /* orders sG writes + prior sW reads vs new sW load */
#pragma unroll
        for (int p = 0; p < 16; ++p) {
            int idx = p * 256 + t;
            int kk = idx >> 6, c4 = idx & 63;
            float4 v = *(const float4*)(Wo + (kc + kk) * 256 + c4 * 4);
            *(float4*)(sW + kk * 256 + c4 * 4) = v;
        }
        __syncthreads();
#pragma unroll 4
        for (int k = 0; k < 64; ++k) {
            float a[8];
#pragma unroll
            for (int j = 0; j < 8; ++j) a[j] = sG[(rg * 8 + j) * 256 + kc + k];
            float4 b0 = *(float4*)(sW + k * 256 + cA);
            float4 b1 = *(float4*)(sW + k * 256 + cB);
#pragma unroll
            for (int j = 0; j < 8; ++j) {
                acc[j * 8 + 0] += a[j] * b0.x; acc[j * 8 + 1] += a[j] * b0.y;
                acc[j * 8 + 2] += a[j] * b0.z; acc[j * 8 + 3] += a[j] * b0.w;
                acc[j * 8 + 4] += a[j] * b1.x; acc[j * 8 + 5] += a[j] * b1.y;
                acc[j * 8 + 6] += a[j] * b1.z; acc[j * 8 + 7] += a[j] * b1.w;
            }
        }
    }

    /* ---- epilogue 2: + bo, * mask, store ---- */
#pragma unroll
    for (int j = 0; j < 8; ++j) {
        int rl = rg * 8 + j;
        int row = row0 + rl;
        float m = sMask[rl];
        float4 o0, o1;
        o0.x = (acc[j * 8 + 0] + sBo[cA + 0]) * m;
        o0.y = (acc[j * 8 + 1] + sBo[cA + 1]) * m;
        o0.z = (acc[j * 8 + 2] + sBo[cA + 2]) * m;
        o0.w = (acc[j * 8 + 3] + sBo[cA + 3]) * m;
        o1.x = (acc[j * 8 + 4] + sBo[cB + 0]) * m;
        o1.y = (acc[j * 8 + 5] + sBo[cB + 1]) * m;
        o1.z = (acc[j * 8 + 6] + sBo[cB + 2]) * m;
        o1.w = (acc[j * 8 + 7] + sBo[cB + 3]) * m;
        *(float4*)(out + (size_t)row * 256 + cA) = o0;
        *(float4*)(out + (size_t)row * 256 + cB) = o1;
    }
}

/* ======================= launch ======================= */
extern "C" void kernel_launch(void* const* d_in, const int* in_sizes, int n_in,
                              void* d_out, int out_size) {
    const float* x    = (const float*)d_in[0];   /* msa_representation [1,512,384,256] */
    const float* mask = (const float*)d_in[1];   /* msa_mask [1,512,384] */
    const float* ln_w = (const float*)d_in[2];
    const float* ln_b = (const float*)d_in[3];
    const float* Wq   = (const float*)d_in[4];
    const float* Wk   = (const float*)d_in[5];
    const float* Wv   = (const float*)d_in[6];
    const float* Wg   = (const float*)d_in[7];
    const float* bg   = (const float*)d_in[8];
    const float* Wo   = (const float*)d_in[9];
    const float* bo   = (const float*)d_in[10];
    float* out = (float*)d_out;

    static bool attr_set = false;
    const int F_SMEM = (64 * 68 + 64 * 256 + 64 * 256 + 256 + 256 + 64) * (int)sizeof(float);
    if (!attr_set) {
        cudaFuncSetAttribute(out_kernel, cudaFuncAttributeMaxDynamicSharedMemorySize, F_SMEM);
        attr_set = true;
    }

    mean_kernel<<<(I_DIM * C_DIM) / 256, 256>>>(x);
    qprep_kernel<<<I_DIM, 256>>>(ln_w, ln_b, Wq, Wk);
    ln_score_kernel<<<R_DIM / 8, 256>>>(x, mask, ln_w, ln_b);
    softmax_kernel<<<H_DIM * I_DIM, 256>>>();
    weighted_kernel<<<I_DIM, 256>>>(Wv);
    out_kernel<<<R_DIM / 64, 256, F_SMEM>>>(Wg, bg, Wo, bo, mask, out);
}

// round 2
// speedup vs baseline: 1.4694x; 1.4694x over previous
#include <cuda_runtime.h>
#include <math.h>

#define S_DIM 512
#define I_DIM 384
#define C_DIM 256
#define H_DIM 8
#define D_DIM 32
#define TD_DIM 256
#define R_DIM (S_DIM * I_DIM)   /* 196608 rows (s,i) */
#define LN_EPS 1e-5f

/* ---------------- scratch (device globals: allocation-free) ---------------- */
__device__ float g_xln[R_DIM * C_DIM];            /* 201 MB : LN(x) rows       */
__device__ float g_scores[H_DIM * I_DIM * S_DIM]; /* [h][i][s]                 */
__device__ float g_attn[I_DIM * H_DIM * S_DIM];   /* [i][h][s]                 */
__device__ float g_mean[I_DIM * C_DIM];           /* column mean of raw x      */
__device__ float g_wkq[I_DIM * H_DIM * C_DIM];    /* Wk @ Q[i,h,:]             */
__device__ float g_weighted[I_DIM * TD_DIM];      /* attn-weighted V           */

/* ============ A: mean over s of raw input -> g_mean[i*C + c] ============ */
__global__ void mean_kernel(const float* __restrict__ x) {
    int idx = blockIdx.x * 256 + threadIdx.x;   /* over I*C = 98304 */
    const float* p = x + idx;
    float acc = 0.f;
#pragma unroll 8
    for (int s = 0; s < S_DIM; ++s) acc += p[s * (I_DIM * C_DIM)];
    g_mean[idx] = acc * (1.0f / S_DIM);
}

/* ============ B: LN(mean) -> Q -> Wkq[i,h,c] (one block per i) ============ */
__global__ void qprep_kernel(const float* __restrict__ ln_w, const float* __restrict__ ln_b,
                             const float* __restrict__ Wq, const float* __restrict__ Wk) {
    __shared__ float sX[C_DIM];
    __shared__ float sQ[TD_DIM];
    __shared__ float sWk[32 * C_DIM];
    __shared__ float red1[8];
    __shared__ float red2[8];
    int t = threadIdx.x;
    int i = blockIdx.x;
    int lane = t & 31, warp = t >> 5;

    float v = g_mean[i * C_DIM + t];
    float sum = v;
#pragma unroll
    for (int o = 16; o; o >>= 1) sum += __shfl_xor_sync(~0u, sum, o);
    if (lane == 0) red1[warp] = sum;
    __syncthreads();
    float tot = red1[0] + red1[1] + red1[2] + red1[3] + red1[4] + red1[5] + red1[6] + red1[7];
    float mu = tot * (1.0f / C_DIM);
    float d = v - mu;
    float sq = d * d;
#pragma unroll
    for (int o = 16; o; o >>= 1) sq += __shfl_xor_sync(~0u, sq, o);
    if (lane == 0) red2[warp] = sq;
    __syncthreads();
    float tot2 = red2[0] + red2[1] + red2[2] + red2[3] + red2[4] + red2[5] + red2[6] + red2[7];
    float var = tot2 * (1.0f / C_DIM);
    float xn = d * rsqrtf(var + LN_EPS) * ln_w[t] + ln_b[t];
    sX[t] = xn;
    __syncthreads();

    /* Q[td] = sX . Wq[:, td] */
    float q = 0.f;
#pragma unroll 4
    for (int c = 0; c < C_DIM; ++c) q += sX[c] * Wq[c * TD_DIM + t];
    sQ[t] = q;
    __syncthreads();

    /* Wkq[i,h,c] = sum_d Q[h*32+d] * Wk[c, h*32+d]   (stage Wk rows in smem) */
    for (int ch = 0; ch < 8; ++ch) {
#pragma unroll
        for (int p = 0; p < 32; ++p) {
            int idx = p * 256 + t;
            sWk[idx] = Wk[(ch * 32) * C_DIM + idx];
        }
        __syncthreads();
        int cl = t >> 3, h = t & 7;
        float a = 0.f;
#pragma unroll
        for (int dd = 0; dd < 32; ++dd)
            a += sQ[h * 32 + dd] * sWk[cl * C_DIM + h * 32 + dd];
        g_wkq[(i * H_DIM + h) * C_DIM + ch * 32 + cl] = a;
        __syncthreads();
    }
}

/* ===== C: per-row LN -> write g_xln; scores[h] = xln . Wkq[i,h,:] (warp/row) ===== */
__global__ void ln_score_kernel(const float* __restrict__ x, const float* __restrict__ mask,
                                const float* __restrict__ ln_w, const float* __restrict__ ln_b) {
    int lane = threadIdx.x & 31;
    int r = blockIdx.x * 8 + (threadIdx.x >> 5);
    int s = r / I_DIM;
    int i = r - s * I_DIM;
    const float* row = x + (size_t)r * C_DIM;

    float xv[8];
#pragma unroll
    for (int j = 0; j < 8; ++j) xv[j] = row[j * 32 + lane];
    float sum = 0.f;
#pragma unroll
    for (int j = 0; j < 8; ++j) sum += xv[j];
#pragma unroll
    for (int o = 16; o; o >>= 1) sum += __shfl_xor_sync(~0u, sum, o);
    float mu = sum * (1.0f / C_DIM);
    float dv[8], sq = 0.f;
#pragma unroll
    for (int j = 0; j < 8; ++j) { dv[j] = xv[j] - mu; sq += dv[j] * dv[j]; }
#pragma unroll
    for (int o = 16; o; o >>= 1) sq += __shfl_xor_sync(~0u, sq, o);
    float rstd = rsqrtf(sq * (1.0f / C_DIM) + LN_EPS);

    float xn[8];
    float* xo = g_xln + (size_t)r * C_DIM;
#pragma unroll
    for (int j = 0; j < 8; ++j) {
        xn[j] = dv[j] * rstd * ln_w[j * 32 + lane] + ln_b[j * 32 + lane];
        xo[j * 32 + lane] = xn[j];
    }

    const float inv_sqrt_d = 0.17677669529663687f; /* 1/sqrt(32) */
    float my_score = 0.f;
#pragma unroll
    for (int h = 0; h < 8; ++h) {
        const float* wk = g_wkq + ((i * H_DIM + h) << 8);
        float p = 0.f;
#pragma unroll
        for (int j = 0; j < 8; ++j) p += xn[j] * wk[j * 32 + lane];
#pragma unroll
        for (int o = 16; o; o >>= 1) p += __shfl_xor_sync(~0u, p, o);
        if (lane == h) my_score = p;
    }
    if (lane < 8) {
        float sc = my_score * inv_sqrt_d + (1.0f - mask[r]) * (-1e9f);
        g_scores[(lane * I_DIM + i) * S_DIM + s] = sc;
    }
}

/* ============ D: softmax over s (block per (h,i)) ============ */
__global__ void softmax_kernel() {
    __shared__ float red[8];
    int bx = blockIdx.x;
    int h = bx / I_DIM;
    int i = bx - h * I_DIM;
    int t = threadIdx.x;
    int lane = t & 31, warp = t >> 5;

    const float* sp = g_scores + (h * I_DIM + i) * S_DIM;
    float v0 = sp[t], v1 = sp[t + 256];
    float m = fmaxf(v0, v1);
#pragma unroll
    for (int o = 16; o; o >>= 1) m = fmaxf(m, __shfl_xor_sync(~0u, m, o));
    if (lane == 0) red[warp] = m;
    __syncthreads();
    m = red[0];
#pragma unroll
    for (int k = 1; k < 8; ++k) m = fmaxf(m, red[k]);
    __syncthreads();
    float e0 = __expf(v0 - m), e1 = __expf(v1 - m);
    float sum = e0 + e1;
#pragma unroll
    for (int o = 16; o; o >>= 1) sum += __shfl_xor_sync(~0u, sum, o);
    if (lane == 0) red[warp] = sum;
    __syncthreads();
    float tot = red[0] + red[1] + red[2] + red[3] + red[4] + red[5] + red[6] + red[7];
    float inv = 1.0f / tot;
    float* op = g_attn + (i * H_DIM + h) * S_DIM;
    op[t] = e0 * inv;
    op[t + 256] = e1 * inv;
}

/* ===== E: Y[i,h,c] = sum_s attn*xln ; weighted[i,h,d] = Y . Wv (block per i) ===== */
__global__ void weighted_kernel(const float* __restrict__ Wv) {
    __shared__ float sA[H_DIM * S_DIM];  /* 16 KB */
    __shared__ float sY[H_DIM * C_DIM];  /*  8 KB */
    int t = threadIdx.x;
    int i = blockIdx.x;
    const float* ap = g_attn + i * H_DIM * S_DIM;
#pragma unroll
    for (int p = 0; p < 16; ++p) sA[p * 256 + t] = ap[p * 256 + t];
    __syncthreads();

    float Y[8];
#pragma unroll
    for (int h = 0; h < 8; ++h) Y[h] = 0.f;
    const float* xp = g_xln + i * C_DIM + t;
#pragma unroll 4
    for (int s2 = 0; s2 < S_DIM; ++s2) {
        float xv = xp[(size_t)s2 * I_DIM * C_DIM];
#pragma unroll
        for (int h = 0; h < 8; ++h) Y[h] += sA[h * S_DIM + s2] * xv;
    }
#pragma unroll
    for (int h = 0; h < 8; ++h) sY[h * C_DIM + t] = Y[h];
    __syncthreads();

    int h = t >> 5, d = t & 31;
    float w = 0.f;
    const float* yp = sY + h * C_DIM;
    const float* wp = Wv + h * 32 + d;
#pragma unroll 4
    for (int c = 0; c < C_DIM; ++c) w += yp[c] * wp[c * TD_DIM];
    g_weighted[i * TD_DIM + t] = w;
}

/* =====================================================================
   F: out = (sigmoid(xln@Wg+bg) * weighted[i]) @ Wo + bo, * mask
   tf32 tensor-core version. Block tile 64(M) x 256(N), 8 warps (2x4),
   warp tile 32x64 = 2x8 mma(m16n8k8) tiles, fp32 accum.
   Chained GEMMs via SMEM (sG holds gated 64x256).
   ===================================================================== */

__device__ __forceinline__ unsigned f2tf32(float f) {
    unsigned u;
    asm("cvt.rna.tf32.f32 %0, %1;" : "=r"(u) : "f"(f));
    return u;
}

#define LDX 76    /* sX leading dim: (8r+? ) -> (76%32=12): conflict-free + float4 aligned */
#define LDW 264   /* sW leading dim: 264%32=8 -> conflict-free + float4 aligned */
#define LDG 260   /* sG leading dim: 260%32=4 -> conflict-free + float4 aligned */

__global__ void __launch_bounds__(256, 1)
out_kernel(const float* __restrict__ Wg, const float* __restrict__ bg,
           const float* __restrict__ Wo, const float* __restrict__ bo,
           const float* __restrict__ mask, float* __restrict__ out) {
    extern __shared__ float sm[];
    float* sX = sm;                  /* 64 x LDX */
    float* sW = sX + 64 * LDX;       /* 64 x LDW */
    float* sG = sW + 64 * LDW;       /* 64 x LDG */
    float* sBg = sG + 64 * LDG;      /* 256 */
    float* sBo = sBg + 256;          /* 256 */
    float* sMask = sBo + 256;        /* 64  */

    const int t = threadIdx.x;
    const int lane = t & 31, w = t >> 5;
    const int wm = (w >> 2) * 32;    /* warp row offset   */
    const int wn = (w & 3) * 64;     /* warp col offset   */
    const int qr = lane >> 2;        /* groupID (0..7)    */
    const int qc = lane & 3;         /* tid-in-group 0..3 */
    const int row0 = blockIdx.x * 64;

    sBg[t] = bg[t];
    sBo[t] = bo[t];
    if (t < 64) sMask[t] = mask[row0 + t];

    float d[2][8][4];
#pragma unroll
    for (int mt = 0; mt < 2; ++mt)
#pragma unroll
        for (int nt = 0; nt < 8; ++nt)
#pragma unroll
            for (int q = 0; q < 4; ++q) d[mt][nt][q] = 0.f;

    const float* xbase = g_xln + (size_t)row0 * C_DIM;

    /* ---------------- GEMM1: xln @ Wg ---------------- */
    for (int kc = 0; kc < 256; kc += 64) {
        __syncthreads();
#pragma unroll
        for (int p = 0; p < 4; ++p) {        /* sX: 64 x 64 chunk */
            int idx = p * 256 + t;
            int rr = idx >> 4, f4 = idx & 15;
            float4 v = *(const float4*)(xbase + (size_t)rr * 256 + kc + f4 * 4);
            *(float4*)(sX + rr * LDX + f4 * 4) = v;
        }
#pragma unroll
        for (int p = 0; p < 16; ++p) {       /* sW: 64 x 256 chunk of Wg */
            int idx = p * 256 + t;
            int kk = idx >> 6, c4 = idx & 63;
            float4 v = *(const float4*)(Wg + (size_t)(kc + kk) * 256 + c4 * 4);
            *(float4*)(sW + kk * LDW + c4 * 4) = v;
        }
        __syncthreads();
#pragma unroll
        for (int k8 = 0; k8 < 64; k8 += 8) {
            unsigned a[2][4], b[8][2];
#pragma unroll
            for (int mt = 0; mt < 2; ++mt) {
                const float* ap = sX + (wm + mt * 16 + qr) * LDX + k8 + qc;
                a[mt][0] = f2tf32(ap[0]);
                a[mt][1] = f2tf32(ap[8 * LDX]);
                a[mt][2] = f2tf32(ap[4]);
                a[mt][3] = f2tf32(ap[8 * LDX + 4]);
            }
#pragma unroll
            for (int nt = 0; nt < 8; ++nt) {
                const float* bp = sW + (k8 + qc) * LDW + wn + nt * 8 + qr;
                b[nt][0] = f2tf32(bp[0]);
                b[nt][1] = f2tf32(bp[4 * LDW]);
            }
#pragma unroll
            for (int mt = 0; mt < 2; ++mt)
#pragma unroll
                for (int nt = 0; nt < 8; ++nt)
                    asm volatile(
                        "mma.sync.aligned.m16n8k8.row.col.f32.tf32.tf32.f32 "
                        "{%0,%1,%2,%3}, {%4,%5,%6,%7}, {%8,%9}, {%0,%1,%2,%3};\n"
                        : "+f"(d[mt][nt][0]), "+f"(d[mt][nt][1]),
                          "+f"(d[mt][nt][2]), "+f"(d[mt][nt][3])
                        : "r"(a[mt][0]), "r"(a[mt][1]), "r"(a[mt][2]), "r"(a[mt][3]),
                          "r"(b[nt][0]), "r"(b[nt][1]));
        }
    }

    /* ---- epilogue 1: sigmoid + gate -> sG ---- */
#pragma unroll
    for (int mt = 0; mt < 2; ++mt) {
#pragma unroll
        for (int rr2 = 0; rr2 < 2; ++rr2) {
            int rl = wm + mt * 16 + qr + rr2 * 8;
            int i = (row0 + rl) % I_DIM;
            const float* wt = g_weighted + i * TD_DIM;
#pragma unroll
            for (int nt = 0; nt < 8; ++nt) {
                int c0 = wn + nt * 8 + qc * 2;
                float v0 = d[mt][nt][rr2 * 2 + 0] + sBg[c0];
                float v1 = d[mt][nt][rr2 * 2 + 1] + sBg[c0 + 1];
                float g0 = 1.0f / (1.0f + __expf(-v0));
                float g1 = 1.0f / (1.0f + __expf(-v1));
                sG[rl * LDG + c0]     = g0 * wt[c0];
                sG[rl * LDG + c0 + 1] = g1 * wt[c0 + 1];
            }
        }
    }
#pragma unroll
    for (int mt = 0; mt < 2; ++mt)
#pragma unroll
        for (int nt = 0; nt < 8; ++nt)
#pragma unroll
            for (int q = 0; q < 4; ++q) d[mt][nt][q] = 0.f;

    /* ---------------- GEMM2: gated @ Wo ---------------- */
    for (int kc = 0; kc < 256; kc += 64) {
        __syncthreads();   /* sG writes done; previous sW readers done */
#pragma unroll
        for (int p = 0; p < 16; ++p) {
            int idx = p * 256 + t;
            int kk = idx >> 6, c4 = idx & 63;
            float4 v = *(const float4*)(Wo + (size_t)(kc + kk) * 256 + c4 * 4);
            *(float4*)(sW + kk * LDW + c4 * 4) = v;
        }
        __syncthreads();
#pragma unroll
        for (int k8 = 0; k8 < 64; k8 += 8) {
            unsigned a[2][4], b[8][2];
#pragma unroll
            for (int mt = 0; mt < 2; ++mt) {
                const float* ap = sG + (wm + mt * 16 + qr) * LDG + kc + k8 + qc;
                a[mt][0] = f2tf32(ap[0]);
                a[mt][1] = f2tf32(ap[8 * LDG]);
                a[mt][2] = f2tf32(ap[4]);
                a[mt][3] = f2tf32(ap[8 * LDG + 4]);
            }
#pragma unroll
            for (int nt = 0; nt < 8; ++nt) {
                const float* bp = sW + (k8 + qc) * LDW + wn + nt * 8 + qr;
                b[nt][0] = f2tf32(bp[0]);
                b[nt][1] = f2tf32(bp[4 * LDW]);
            }
#pragma unroll
            for (int mt = 0; mt < 2; ++mt)
#pragma unroll
                for (int nt = 0; nt < 8; ++nt)
                    asm volatile(
                        "mma.sync.aligned.m16n8k8.row.col.f32.tf32.tf32.f32 "
                        "{%0,%1,%2,%3}, {%4,%5,%6,%7}, {%8,%9}, {%0,%1,%2,%3};\n"
                        : "+f"(d[mt][nt][0]), "+f"(d[mt][nt][1]),
                          "+f"(d[mt][nt][2]), "+f"(d[mt][nt][3])
                        : "r"(a[mt][0]), "r"(a[mt][1]), "r"(a[mt][2]), "r"(a[mt][3]),
                          "r"(b[nt][0]), "r"(b[nt][1]));
        }
    }

    /* ---- epilogue 2: + bo, * mask -> sG, then coalesced float4 store ---- */
    __syncthreads();   /* all sG reads (GEMM2 A-frags) complete before overwrite */
#pragma unroll
    for (int mt = 0; mt < 2; ++mt) {
#pragma unroll
        for (int rr2 = 0; rr2 < 2; ++rr2) {
            int rl = wm + mt * 16 + qr + rr2 * 8;
            float m = sMask[rl];
#pragma unroll
            for (int nt = 0; nt < 8; ++nt) {
                int c0 = wn + nt * 8 + qc * 2;
                sG[rl * LDG + c0]     = (d[mt][nt][rr2 * 2 + 0] + sBo[c0]) * m;
                sG[rl * LDG + c0 + 1] = (d[mt][nt][rr2 * 2 + 1] + sBo[c0 + 1]) * m;
            }
        }
    }
    __syncthreads();
#pragma unroll
    for (int p = 0; p < 16; ++p) {
        int idx = p * 256 + t;
        int rr = idx >> 6, c4 = idx & 63;
        float4 v = *(float4*)(sG + rr * LDG + c4 * 4);
        *(float4*)(out + (size_t)(row0 + rr) * 256 + c4 * 4) = v;
    }
}

/* ======================= launch ======================= */
extern "C" void kernel_launch(void* const* d_in, const int* in_sizes, int n_in,
                              void* d_out, int out_size) {
    const float* x    = (const float*)d_in[0];   /* msa_representation [1,512,384,256] */
    const float* mask = (const float*)d_in[1];   /* msa_mask [1,512,384] */
    const float* ln_w = (const float*)d_in[2];
    const float* ln_b = (const float*)d_in[3];
    const float* Wq   = (const float*)d_in[4];
    const float* Wk   = (const float*)d_in[5];
    const float* Wv   = (const float*)d_in[6];
    const float* Wg   = (const float*)d_in[7];
    const float* bg   = (const float*)d_in[8];
    const float* Wo   = (const float*)d_in[9];
    const float* bo   = (const float*)d_in[10];
    float* out = (float*)d_out;

    static bool attr_set = false;
    const int F_SMEM = (64 * LDX + 64 * LDW + 64 * LDG + 256 + 256 + 64) * (int)sizeof(float);
    if (!attr_set) {
        cudaFuncSetAttribute(out_kernel, cudaFuncAttributeMaxDynamicSharedMemorySize, F_SMEM);
        attr_set = true;
    }

    mean_kernel<<<(I_DIM * C_DIM) / 256, 256>>>(x);
    qprep_kernel<<<I_DIM, 256>>>(ln_w, ln_b, Wq, Wk);
    ln_score_kernel<<<R_DIM / 8, 256>>>(x, mask, ln_w, ln_b);
    softmax_kernel<<<H_DIM * I_DIM, 256>>>();
    weighted_kernel<<<I_DIM, 256>>>(Wv);
    out_kernel<<<R_DIM / 64, 256, F_SMEM>>>(Wg, bg, Wo, bo, mask, out);
}